// round 2
// baseline (speedup 1.0000x reference)
#include <cuda_runtime.h>
#include <stdint.h>

// out[N,32] = segment_sum_e( edge_val[e] * weight[edge_col[e], :] ) into row edge_row[e], + bias
// Inputs (metadata order) — NOTE: JAX demotes int64->int32 without x64 mode:
//   d_in[0] = edge_row  int32  [E]
//   d_in[1] = edge_col  int32  [E]
//   d_in[2] = edge_val  f32    [E]
//   d_in[3] = weight    f32    [N*32]
//   d_in[4] = bias      f32    [32]
// d_out = f32 [N*32]

static constexpr int D = 32;

__global__ void init_bias_kernel(float* __restrict__ out,
                                 const float* __restrict__ bias,
                                 int total) {
    int i = blockIdx.x * blockDim.x + threadIdx.x;
    if (i < total) {
        out[i] = __ldg(&bias[i & (D - 1)]);
    }
}

// One warp per edge; lane = feature index. Row/col/val loads are warp-uniform
// (hardware broadcast); weight load + atomic are coalesced 128B.
__global__ void spmm_coo_kernel(const int* __restrict__ edge_row,
                                const int* __restrict__ edge_col,
                                const float* __restrict__ edge_val,
                                const float* __restrict__ weight,
                                float* __restrict__ out,
                                int E) {
    int gtid = blockIdx.x * blockDim.x + threadIdx.x;
    int e    = gtid >> 5;          // warp id == edge id
    int lane = gtid & 31;          // feature id
    if (e >= E) return;

    int   r = edge_row[e];         // uniform within warp -> broadcast
    int   c = edge_col[e];
    float v = edge_val[e];

    float w = __ldg(&weight[(long long)c * D + lane]);
    atomicAdd(&out[(long long)r * D + lane], v * w);
}

extern "C" void kernel_launch(void* const* d_in, const int* in_sizes, int n_in,
                              void* d_out, int out_size) {
    const int*   edge_row = (const int*)d_in[0];
    const int*   edge_col = (const int*)d_in[1];
    const float* edge_val = (const float*)d_in[2];
    const float* weight   = (const float*)d_in[3];
    const float* bias     = (const float*)d_in[4];
    float*       out      = (float*)d_out;

    const int E = in_sizes[2];           // edge count
    const int total = out_size;          // N * 32

    {
        int threads = 256;
        int blocks = (total + threads - 1) / threads;
        init_bias_kernel<<<blocks, threads>>>(out, bias, total);
    }
    {
        long long work = (long long)E * 32;
        int threads = 256;
        int blocks = (int)((work + threads - 1) / threads);
        spmm_coo_kernel<<<blocks, threads>>>(edge_row, edge_col, edge_val,
                                             weight, out, E);
    }
}

// round 3
// speedup vs baseline: 2.5993x; 2.5993x over previous
#include <cuda_runtime.h>
#include <stdint.h>

// out[N,32] = segment_sum_e( edge_val[e] * weight[edge_col[e], :] ) into row edge_row[e], + bias
// Inputs (metadata order) — JAX demotes int64->int32 (x64 disabled):
//   d_in[0] = edge_row  int32  [E]
//   d_in[1] = edge_col  int32  [E]
//   d_in[2] = edge_val  f32    [E]
//   d_in[3] = weight    f32    [N*32]
//   d_in[4] = bias      f32    [32]
// d_out = f32 [N*32]

static constexpr int D = 32;
static constexpr int EDGES_PER_ITER = 4;   // 8 lanes per edge (8 x float4 = 32 feats)
static constexpr int ITERS_PER_WARP = 4;   // unrolled; 16 contiguous edges per warp
static constexpr int EDGES_PER_WARP = EDGES_PER_ITER * ITERS_PER_WARP;

__device__ __forceinline__ void red_add_v4(float* addr, float4 v) {
    asm volatile("red.global.add.v4.f32 [%0], {%1, %2, %3, %4};"
                 :: "l"(addr), "f"(v.x), "f"(v.y), "f"(v.z), "f"(v.w)
                 : "memory");
}

__global__ void init_bias_kernel(float4* __restrict__ out4,
                                 const float4* __restrict__ bias4,
                                 int total4) {
    int i = blockIdx.x * blockDim.x + threadIdx.x;
    if (i < total4) {
        out4[i] = bias4[i & 7];           // 32 floats = 8 float4
    }
}

// 8 lanes per edge, each lane owns a float4 of features.
// Per warp-iteration: 4 edges. 4 unrolled iterations -> 16 edges in flight,
// giving front-batched independent LDG.128s (high MLP) and 4x fewer
// load/atomic instructions than the scalar version.
__global__ void spmm_coo_v4_kernel(const int*   __restrict__ edge_row,
                                   const int*   __restrict__ edge_col,
                                   const float* __restrict__ edge_val,
                                   const float4* __restrict__ weight4,  // [N*8]
                                   float*        __restrict__ out,
                                   int E) {
    int gtid    = blockIdx.x * blockDim.x + threadIdx.x;
    int warp_id = gtid >> 5;
    int lane    = gtid & 31;
    int sub     = lane >> 3;               // edge within group of 4
    int feat4   = lane & 7;                // which float4 of the 32 features

    int e_base = warp_id * EDGES_PER_WARP;

#pragma unroll
    for (int it = 0; it < ITERS_PER_WARP; ++it) {
        int e = e_base + it * EDGES_PER_ITER + sub;
        if (e < E) {
            int   r = edge_row[e];         // 4 distinct values/warp -> 1 sector
            int   c = edge_col[e];
            float v = edge_val[e];

            float4 w = __ldg(&weight4[(long long)c * 8 + feat4]);  // LDG.128
            float4 contrib = make_float4(v * w.x, v * w.y, v * w.z, v * w.w);
            red_add_v4(&out[((long long)r * D) + feat4 * 4], contrib);
        }
    }
}

extern "C" void kernel_launch(void* const* d_in, const int* in_sizes, int n_in,
                              void* d_out, int out_size) {
    const int*    edge_row = (const int*)d_in[0];
    const int*    edge_col = (const int*)d_in[1];
    const float*  edge_val = (const float*)d_in[2];
    const float4* weight4  = (const float4*)d_in[3];
    const float4* bias4    = (const float4*)d_in[4];
    float*        out      = (float*)d_out;

    const int E      = in_sizes[2];        // edge count
    const int total4 = out_size / 4;       // N * 8

    {
        int threads = 256;
        int blocks  = (total4 + threads - 1) / threads;
        init_bias_kernel<<<blocks, threads>>>((float4*)out, bias4, total4);
    }
    {
        int warps   = (E + EDGES_PER_WARP - 1) / EDGES_PER_WARP;
        int threads = 256;                 // 8 warps/block
        int blocks  = (warps + 7) / 8;
        spmm_coo_v4_kernel<<<blocks, threads>>>(edge_row, edge_col, edge_val,
                                                weight4, out, E);
    }
}